// round 11
// baseline (speedup 1.0000x reference)
#include <cuda_runtime.h>
#include <cstdint>

// Problem constants
#define B_ 64
#define L_ 512
#define P_ 64
#define A_ 16
#define F_ 80
#define D_ 512

// Scan organization
#define CSZ 8       // CTAs per cluster (column split of R)
#define NCL 16      // clusters (B_/ROWS)
#define ROWS 4      // batch rows per cluster
#define COLS 64     // columns per CTA
#define KROWS 32    // rows per warp k-slice (16 warps)
#define THREADS 512

// Scratch
__device__ float g_ci[B_ * L_ * D_];      // tanh(x@W_ci+b)

// ---- f32x2 helpers --------------------------------------------------------
__device__ __forceinline__ unsigned long long pk2(float lo, float hi) {
    unsigned long long r;
    asm("mov.b64 %0, {%1,%2};" : "=l"(r) : "f"(lo), "f"(hi));
    return r;
}
__device__ __forceinline__ void fma2(unsigned long long& d, unsigned long long a, unsigned long long b) {
    asm("fma.rn.f32x2 %0, %1, %2, %0;" : "+l"(d) : "l"(a), "l"(b));
}
__device__ __forceinline__ void upk2(float& lo, float& hi, unsigned long long v) {
    asm("mov.b64 {%0,%1}, %2;" : "=f"(lo), "=f"(hi) : "l"(v));
}

// ---- mbarrier / bulk-DSMEM helpers ----------------------------------------
__device__ __forceinline__ void mbar_init(uint32_t addr, uint32_t cnt) {
    asm volatile("mbarrier.init.shared.b64 [%0], %1;" :: "r"(addr), "r"(cnt) : "memory");
}
__device__ __forceinline__ void mbar_expect_tx(uint32_t addr, uint32_t bytes) {
    asm volatile("mbarrier.arrive.expect_tx.shared.b64 _, [%0], %1;"
                 :: "r"(addr), "r"(bytes) : "memory");
}
__device__ __forceinline__ void mbar_wait_cta(uint32_t addr, uint32_t parity) {
    uint32_t done;
    asm volatile(
        "{\n\t.reg .pred p;\n\t"
        "mbarrier.try_wait.parity.acquire.cta.shared::cta.b64 p, [%1], %2;\n\t"
        "selp.b32 %0, 1, 0, p;\n\t}"
        : "=r"(done) : "r"(addr), "r"(parity) : "memory");
    if (!done) {
        asm volatile(
            "{\n\t.reg .pred P1;\n\t"
            "WL_%=:\n\t"
            "mbarrier.try_wait.parity.acquire.cta.shared::cta.b64 P1, [%0], %1, 0x989680;\n\t"
            "@P1 bra.uni WD_%=;\n\t"
            "bra.uni WL_%=;\n\t"
            "WD_%=:\n\t}"
            :: "r"(addr), "r"(parity) : "memory");
    }
}
__device__ __forceinline__ void bulk_dsmem(uint32_t dst, uint32_t src,
                                           uint32_t bytes, uint32_t mbar) {
    asm volatile(
        "cp.async.bulk.shared::cluster.shared::cta.mbarrier::complete_tx::bytes "
        "[%0], [%1], %2, [%3];"
        :: "r"(dst), "r"(src), "r"(bytes), "r"(mbar) : "memory");
}
__device__ __forceinline__ void fence_proxy_async_cta() {
    asm volatile("fence.proxy.async.shared::cta;" ::: "memory");
}

// ============================================================================
// Kernel 1: ci = tanh(x @ W_ci + b_ci)
// x stored TRANSPOSED in smem (xs_t[k][row], pad 68) so the A operand loads
// as one LDS.128 per k instead of 4 scalar LDS (ncu: L1=45% was the cap).
// ============================================================================
#define XST 68   // padded row stride (floats); 68*4=272 B (16B mult)

__global__ __launch_bounds__(256)
void k_ci(const float* __restrict__ obs, const float* __restrict__ act,
          const float* __restrict__ W, const float* __restrict__ bci)
{
    __shared__ float xs_t[80 * XST];   // [k][row]
    __shared__ float ws[80 * 64];      // [k][d]

    const int tid  = threadIdx.x;
    const int row0 = blockIdx.y * 64;
    const int d0   = blockIdx.x * 64;

    for (int idx = tid; idx < 64 * 80; idx += 256) {
        int r = idx / 80, c = idx % 80;
        int blg = row0 + r;
        int b = blg >> 9, l = blg & 511;
        float v = (c < 64) ? obs[(b * L_ + l) * P_ + c]
                           : act[(b * L_ + l) * A_ + (c - 64)];
        xs_t[c * XST + r] = v;
    }
    for (int idx = tid; idx < 80 * 64; idx += 256) {
        int k = idx >> 6, d = idx & 63;
        ws[k * 64 + d] = W[k * D_ + d0 + d];
    }
    __syncthreads();

    const int tx = tid & 15, ty = tid >> 4;
    float acc[4][4] = {};
#pragma unroll
    for (int k = 0; k < 80; k++) {
        float4 av = *(const float4*)&xs_t[k * XST + ty * 4];
        float4 bv = *(const float4*)&ws[k * 64 + tx * 4];
        acc[0][0] += av.x * bv.x; acc[0][1] += av.x * bv.y; acc[0][2] += av.x * bv.z; acc[0][3] += av.x * bv.w;
        acc[1][0] += av.y * bv.x; acc[1][1] += av.y * bv.y; acc[1][2] += av.y * bv.z; acc[1][3] += av.y * bv.w;
        acc[2][0] += av.z * bv.x; acc[2][1] += av.z * bv.y; acc[2][2] += av.z * bv.z; acc[2][3] += av.z * bv.w;
        acc[3][0] += av.w * bv.x; acc[3][1] += av.w * bv.y; acc[3][2] += av.w * bv.z; acc[3][3] += av.w * bv.w;
    }

    float bi0 = bci[d0 + tx * 4 + 0];
    float bi1 = bci[d0 + tx * 4 + 1];
    float bi2 = bci[d0 + tx * 4 + 2];
    float bi3 = bci[d0 + tx * 4 + 3];
#pragma unroll
    for (int ii = 0; ii < 4; ii++) {
        int blg = row0 + ty * 4 + ii;
        float4 o;
        o.x = tanhf(acc[ii][0] + bi0);
        o.y = tanhf(acc[ii][1] + bi1);
        o.z = tanhf(acc[ii][2] + bi2);
        o.w = tanhf(acc[ii][3] + bi3);
        *(float4*)&g_ci[blg * D_ + d0 + tx * 4] = o;
    }
}

// ============================================================================
// Kernel 2: the scan — R10 sync topology unchanged. New: output partials
// ride the h DMA slice (slice = 256 h floats + 32 osum partials + pad = 292
// floats = 1168 B). Warps 8-15 consume all 64 partials during the reduce
// phase (they were idle there) and CTA 0 writes out[] directly.
// k_out and g_part are eliminated.
//
// SMEM (floats):
//   hbuf [0, 7008)        3 bufs x 8 slices x 292   (h[col][b] | osum | pad)
//   pbuf [7008, 11104)    512 x 8
//   bias [11104, 11168)
//   wsl  [11168, 11232)
//   mbar @ byte 44928 (3 x 8 B)
// ============================================================================
#define SLICE_F   292                     // 256 h + 32 osum + 4 pad
#define SLICE_BYTES (SLICE_F * 4)         // 1168 (16B multiple)
#define HB_STRIDE (CSZ * SLICE_F)         // 2336 floats per buffer
#define HBUF_OFF  0
#define PBUF_OFF  (3 * HB_STRIDE)         // 7008
#define BIAS_OFF  (PBUF_OFF + 4096)       // 11104
#define WSL_OFF   (BIAS_OFF + 64)         // 11168
#define MBAR_BYTE ((WSL_OFF + 64) * 4)    // 44928
#define SMEM_BYTES (MBAR_BYTE + 64)

#define STEP_TX   ((CSZ - 1) * SLICE_BYTES)   // 8176

extern __shared__ float smem_f[];

__global__ void __cluster_dims__(CSZ, 1, 1) __launch_bounds__(THREADS, 1)
k_scan(const float* __restrict__ R, const float* __restrict__ b_ig,
       const float* __restrict__ W_out, const float* __restrict__ b_out,
       float* __restrict__ out)
{
    float* hbuf = smem_f + HBUF_OFF;
    float* pbuf = smem_f + PBUF_OFF;
    float* bias = smem_f + BIAS_OFF;
    float* wsl  = smem_f + WSL_OFF;

    const uint32_t smem_u32 = (uint32_t)__cvta_generic_to_shared(smem_f);

    const int tid = threadIdx.x;
    const int c   = blockIdx.x;          // cluster rank / column slice
    const int b0  = blockIdx.y * ROWS;
    const int j0  = c * COLS;

    const int ks = tid >> 5;             // warp = k-slice (0..15)
    const int jp = tid & 31;             // cols 2jp, 2jp+1
    const int jj = tid >> 2;             // reduce mapping (tid<256)
    const int bb = tid & 3;

    // consumer mapping (warp 8: tid 256..287)
    const int cb = (tid - 256) >> 3;     // batch 0..3
    const int cs = tid & 7;              // slice 0..7

    // ---- R slice into registers ----
    float rx[KROWS], ry[KROWS];
    {
        const float* rg = R + j0 + 2 * jp;
#pragma unroll
        for (int ii = 0; ii < KROWS; ii++) {
            float2 v = *(const float2*)(rg + (ks * KROWS + ii) * D_);
            rx[ii] = v.x; ry[ii] = v.y;
        }
    }

    // ---- init smem ----
    for (int idx = tid; idx < 3 * HB_STRIDE; idx += THREADS) hbuf[idx] = 0.0f;
    if (tid < COLS) {
        bias[tid] = b_ig[j0 + tid];
        wsl[tid]  = W_out[j0 + tid];
    }
    if (tid == 0) {
        mbar_init(smem_u32 + MBAR_BYTE + 0,  1);
        mbar_init(smem_u32 + MBAR_BYTE + 8,  1);
        mbar_init(smem_u32 + MBAR_BYTE + 16, 1);
    }
    __syncthreads();
    if (tid == 0) {
        mbar_expect_tx(smem_u32 + MBAR_BYTE + 0,  STEP_TX);
        mbar_expect_tx(smem_u32 + MBAR_BYTE + 8,  STEP_TX);
        mbar_expect_tx(smem_u32 + MBAR_BYTE + 16, STEP_TX);
    }
    __syncthreads();
    asm volatile("barrier.cluster.arrive.aligned;" ::: "memory");
    asm volatile("barrier.cluster.wait.aligned;"   ::: "memory");

    // Peer smem bases
    uint32_t peer_base[CSZ];
#pragma unroll
    for (int p = 0; p < CSZ; p++) {
        asm volatile("mapa.shared::cluster.u32 %0, %1, %2;"
                     : "=r"(peer_base[p]) : "r"(smem_u32), "r"(p));
    }

    const float bout = b_out[0];
    float racc = 0.0f;                  // live in warp 8 lanes
    int cur = 0;
    uint32_t phases = 0;                // bit b = next wait parity for buffer b

    for (int t = 0; t < L_; t++) {
        const int nxt = (cur == 2) ? 0 : cur + 1;

        // prefetch ci (consumed after matvec)
        float civ = 0.0f;
        if (tid < 256)
            civ = __ldg(&g_ci[((b0 + bb) * L_ + t) * D_ + j0 + jj]);

        // wait for h(t) remote slices + osum(t-1) partials
        if (t > 0) {
            mbar_wait_cta(smem_u32 + MBAR_BYTE + cur * 8, (phases >> cur) & 1u);
            phases ^= (1u << cur);
            if (tid == 256)
                mbar_expect_tx(smem_u32 + MBAR_BYTE + cur * 8, STEP_TX);
        }

        float* hc = hbuf + cur * HB_STRIDE;

        // ---- matvec: R from registers, h broadcast from smem (slice-major) ----
        {
            const ulonglong2* hvp =
                (const ulonglong2*)(hc + (ks >> 1) * SLICE_F + (ks & 1) * 128);
            unsigned long long a00 = 0, a01 = 0, a10 = 0, a11 = 0;
#pragma unroll
            for (int ii = 0; ii < KROWS; ii++) {
                ulonglong2 hv = hvp[ii];
                unsigned long long r0 = pk2(rx[ii], rx[ii]);
                unsigned long long r1 = pk2(ry[ii], ry[ii]);
                fma2(a00, r0, hv.x); fma2(a01, r0, hv.y);
                fma2(a10, r1, hv.x); fma2(a11, r1, hv.y);
            }
            float4 q0, q1;
            upk2(q0.x, q0.y, a00); upk2(q0.z, q0.w, a01);
            upk2(q1.x, q1.y, a10); upk2(q1.z, q1.w, a11);
            float* pb = pbuf + (ks * 32 + jp) * 8;
            *(float4*)(pb)     = q0;
            *(float4*)(pb + 4) = q1;
        }
        __syncthreads();

        // ---- reduce + gate + update (warps 0-7) ----
        if (tid < 256) {
            float p0 = pbuf[0 * 256 + tid], p1 = pbuf[1 * 256 + tid];
            float p2 = pbuf[2 * 256 + tid], p3 = pbuf[3 * 256 + tid];
            float p4 = pbuf[4 * 256 + tid], p5 = pbuf[5 * 256 + tid];
            float p6 = pbuf[6 * 256 + tid], p7 = pbuf[7 * 256 + tid];
            float p8 = pbuf[8 * 256 + tid], p9 = pbuf[9 * 256 + tid];
            float pa = pbuf[10 * 256 + tid], pc2 = pbuf[11 * 256 + tid];
            float pd = pbuf[12 * 256 + tid], pe = pbuf[13 * 256 + tid];
            float pf = pbuf[14 * 256 + tid], pg = pbuf[15 * 256 + tid];
            float z = bias[jj]
                    + (((p0 + p1) + (p2 + p3)) + ((p4 + p5) + (p6 + p7)))
                    + (((p8 + p9) + (pa + pc2)) + ((pd + pe) + (pf + pg)));
            float ig = 1.0f / (1.0f + __expf(-z));
            float u  = civ * ig;
            float hval = hc[c * SLICE_F + jj * 4 + bb] + u;
            hbuf[nxt * HB_STRIDE + c * SLICE_F + jj * 4 + bb] = hval;

            float pp = u * wsl[jj];
            pp += __shfl_xor_sync(0xFFFFFFFF, pp, 4);
            pp += __shfl_xor_sync(0xFFFFFFFF, pp, 8);
            pp += __shfl_xor_sync(0xFFFFFFFF, pp, 16);
            if ((tid & 31) < 4)
                hbuf[nxt * HB_STRIDE + c * SLICE_F + 256 + (tid >> 5) * 4 + bb] = pp;
        }
        // ---- warp 8 consumes osum(t-1) in parallel with the reduce ----
        else if (t > 0 && tid < 288) {
            float s = 0.0f;
#pragma unroll
            for (int w = 0; w < 8; w++)
                s += hc[cs * SLICE_F + 256 + w * 4 + cb];
            s += __shfl_xor_sync(0xFFFFFFFF, s, 1);
            s += __shfl_xor_sync(0xFFFFFFFF, s, 2);
            s += __shfl_xor_sync(0xFFFFFFFF, s, 4);
            racc += s;
            if (c == 0 && cs == 0)
                out[(b0 + cb) * L_ + (t - 1)] = racc + bout;
        }
        __syncthreads();

        // ---- DMA h(t+1) slice (+osum(t)) to the 7 remote peers ----
        if (tid < CSZ && tid != c) {
            fence_proxy_async_cta();
            uint32_t off  = (uint32_t)(HBUF_OFF + nxt * HB_STRIDE + c * SLICE_F) * 4u;
            uint32_t moff = (uint32_t)(MBAR_BYTE + nxt * 8);
            bulk_dsmem(peer_base[tid] + off, smem_u32 + off, SLICE_BYTES,
                       peer_base[tid] + moff);
        }

        cur = nxt;
    }

    // ---- final round: collect osum(L-1) delivered by the t=511 DMA ----
    if (tid >= 256 && tid < 288) {
        mbar_wait_cta(smem_u32 + MBAR_BYTE + cur * 8, (phases >> cur) & 1u);
        const float* hcf = hbuf + cur * HB_STRIDE;
        float s = 0.0f;
#pragma unroll
        for (int w = 0; w < 8; w++)
            s += hcf[cs * SLICE_F + 256 + w * 4 + cb];
        s += __shfl_xor_sync(0xFFFFFFFF, s, 1);
        s += __shfl_xor_sync(0xFFFFFFFF, s, 2);
        s += __shfl_xor_sync(0xFFFFFFFF, s, 4);
        racc += s;
        if (c == 0 && cs == 0)
            out[(b0 + cb) * L_ + (L_ - 1)] = racc + bout;
    }
    __syncthreads();

    asm volatile("barrier.cluster.arrive.aligned;" ::: "memory");
    asm volatile("barrier.cluster.wait.aligned;"   ::: "memory");
}

// ============================================================================
extern "C" void kernel_launch(void* const* d_in, const int* in_sizes, int n_in,
                              void* d_out, int out_size)
{
    const float* obs  = (const float*)d_in[0];
    const float* act  = (const float*)d_in[1];
    const float* W_ci = (const float*)d_in[2];
    const float* b_ci = (const float*)d_in[3];
    const float* R    = (const float*)d_in[4];
    const float* bg   = (const float*)d_in[5];
    const float* W_o  = (const float*)d_in[6];
    const float* b_o  = (const float*)d_in[7];
    float* out = (float*)d_out;

    k_ci<<<dim3(8, 512), 256>>>(obs, act, W_ci, b_ci);

    cudaFuncSetAttribute(k_scan, cudaFuncAttributeMaxDynamicSharedMemorySize, SMEM_BYTES);
    k_scan<<<dim3(CSZ, NCL), THREADS, SMEM_BYTES>>>(R, bg, W_o, b_o, out);
}

// round 12
// speedup vs baseline: 1.1147x; 1.1147x over previous
#include <cuda_runtime.h>
#include <cstdint>

// Problem constants
#define B_ 64
#define L_ 512
#define P_ 64
#define A_ 16
#define F_ 80
#define D_ 512

// Scan organization
#define CSZ 8       // CTAs per cluster (column split of R)
#define NCL 16      // clusters (B_/ROWS)
#define ROWS 4      // batch rows per cluster
#define COLS 64     // columns per CTA
#define KROWS 32    // rows per warp k-slice (16 warps)
#define THREADS 512

// Scratch
__device__ float g_ci[B_ * L_ * D_];      // tanh(x@W_ci+b)
__device__ float g_part[B_ * CSZ * L_];   // per-CTA cumulative output partials

// ---- f32x2 helpers --------------------------------------------------------
__device__ __forceinline__ unsigned long long pk2(float lo, float hi) {
    unsigned long long r;
    asm("mov.b64 %0, {%1,%2};" : "=l"(r) : "f"(lo), "f"(hi));
    return r;
}
__device__ __forceinline__ void fma2(unsigned long long& d, unsigned long long a, unsigned long long b) {
    asm("fma.rn.f32x2 %0, %1, %2, %0;" : "+l"(d) : "l"(a), "l"(b));
}
__device__ __forceinline__ void upk2(float& lo, float& hi, unsigned long long v) {
    asm("mov.b64 {%0,%1}, %2;" : "=f"(lo), "=f"(hi) : "l"(v));
}

// ---- mbarrier / bulk-DSMEM helpers ----------------------------------------
__device__ __forceinline__ void mbar_init(uint32_t addr, uint32_t cnt) {
    asm volatile("mbarrier.init.shared.b64 [%0], %1;" :: "r"(addr), "r"(cnt) : "memory");
}
__device__ __forceinline__ void mbar_expect_tx(uint32_t addr, uint32_t bytes) {
    asm volatile("mbarrier.arrive.expect_tx.shared.b64 _, [%0], %1;"
                 :: "r"(addr), "r"(bytes) : "memory");
}
__device__ __forceinline__ void mbar_wait_cta(uint32_t addr, uint32_t parity) {
    uint32_t done;
    asm volatile(
        "{\n\t.reg .pred p;\n\t"
        "mbarrier.try_wait.parity.acquire.cta.shared::cta.b64 p, [%1], %2;\n\t"
        "selp.b32 %0, 1, 0, p;\n\t}"
        : "=r"(done) : "r"(addr), "r"(parity) : "memory");
    if (!done) {
        asm volatile(
            "{\n\t.reg .pred P1;\n\t"
            "WL_%=:\n\t"
            "mbarrier.try_wait.parity.acquire.cta.shared::cta.b64 P1, [%0], %1, 0x989680;\n\t"
            "@P1 bra.uni WD_%=;\n\t"
            "bra.uni WL_%=;\n\t"
            "WD_%=:\n\t}"
            :: "r"(addr), "r"(parity) : "memory");
    }
}
__device__ __forceinline__ void bulk_dsmem(uint32_t dst, uint32_t src,
                                           uint32_t bytes, uint32_t mbar) {
    asm volatile(
        "cp.async.bulk.shared::cluster.shared::cta.mbarrier::complete_tx::bytes "
        "[%0], [%1], %2, [%3];"
        :: "r"(dst), "r"(src), "r"(bytes), "r"(mbar) : "memory");
}
__device__ __forceinline__ void fence_proxy_async_cta() {
    asm volatile("fence.proxy.async.shared::cta;" ::: "memory");
}

// ============================================================================
// Kernel 1: ci = tanh(x @ W_ci + b_ci)
// x stored TRANSPOSED in smem (xs_t[k][row], pad 68): A-operand becomes one
// LDS.128 per k (2 distinct addrs/warp) instead of 4 scalar LDS.
// (R10 ncu: L1=45% > fma=31% — smem-wavefront-bound.)
// ============================================================================
#define XST 68   // padded row stride (floats)

__global__ __launch_bounds__(256)
void k_ci(const float* __restrict__ obs, const float* __restrict__ act,
          const float* __restrict__ W, const float* __restrict__ bci)
{
    __shared__ float xs_t[80 * XST];   // [k][row]
    __shared__ float ws[80 * 64];      // [k][d]

    const int tid  = threadIdx.x;
    const int row0 = blockIdx.y * 64;
    const int d0   = blockIdx.x * 64;

    for (int idx = tid; idx < 64 * 80; idx += 256) {
        int r = idx / 80, c = idx % 80;
        int blg = row0 + r;
        int b = blg >> 9, l = blg & 511;
        float v = (c < 64) ? obs[(b * L_ + l) * P_ + c]
                           : act[(b * L_ + l) * A_ + (c - 64)];
        xs_t[c * XST + r] = v;
    }
    for (int idx = tid; idx < 80 * 64; idx += 256) {
        int k = idx >> 6, d = idx & 63;
        ws[k * 64 + d] = W[k * D_ + d0 + d];
    }
    __syncthreads();

    const int tx = tid & 15, ty = tid >> 4;
    float acc[4][4] = {};
#pragma unroll
    for (int k = 0; k < 80; k++) {
        float4 av = *(const float4*)&xs_t[k * XST + ty * 4];
        float4 bv = *(const float4*)&ws[k * 64 + tx * 4];
        acc[0][0] += av.x * bv.x; acc[0][1] += av.x * bv.y; acc[0][2] += av.x * bv.z; acc[0][3] += av.x * bv.w;
        acc[1][0] += av.y * bv.x; acc[1][1] += av.y * bv.y; acc[1][2] += av.y * bv.z; acc[1][3] += av.y * bv.w;
        acc[2][0] += av.z * bv.x; acc[2][1] += av.z * bv.y; acc[2][2] += av.z * bv.z; acc[2][3] += av.z * bv.w;
        acc[3][0] += av.w * bv.x; acc[3][1] += av.w * bv.y; acc[3][2] += av.w * bv.z; acc[3][3] += av.w * bv.w;
    }

    float bi0 = bci[d0 + tx * 4 + 0];
    float bi1 = bci[d0 + tx * 4 + 1];
    float bi2 = bci[d0 + tx * 4 + 2];
    float bi3 = bci[d0 + tx * 4 + 3];
#pragma unroll
    for (int ii = 0; ii < 4; ii++) {
        int blg = row0 + ty * 4 + ii;
        float4 o;
        o.x = tanhf(acc[ii][0] + bi0);
        o.y = tanhf(acc[ii][1] + bi1);
        o.z = tanhf(acc[ii][2] + bi2);
        o.w = tanhf(acc[ii][3] + bi3);
        *(float4*)&g_ci[blg * D_ + d0 + tx * 4] = o;
    }
}

// ============================================================================
// Kernel 2: the scan — EXACT R10 code (1487 us, known good). Untouched.
// ============================================================================
#define HBUF_OFF  0
#define PBUF_OFF  6144
#define BIAS_OFF  10240
#define WSL_OFF   10304
#define OSUM_OFF  10368
#define MBAR_BYTE 41600
#define SMEM_BYTES (MBAR_BYTE + 64)

#define SLICE_BYTES 1024                       // 64 cols x 4 batches x 4 B
#define STEP_TX     ((CSZ - 1) * SLICE_BYTES)  // 7168 (self-copy skipped)

extern __shared__ float smem_f[];

__global__ void __cluster_dims__(CSZ, 1, 1) __launch_bounds__(THREADS, 1)
k_scan(const float* __restrict__ R, const float* __restrict__ b_ig,
       const float* __restrict__ W_out)
{
    float* hbuf = smem_f + HBUF_OFF;
    float* pbuf = smem_f + PBUF_OFF;
    float* bias = smem_f + BIAS_OFF;
    float* wsl  = smem_f + WSL_OFF;
    float* osum = smem_f + OSUM_OFF;

    const uint32_t smem_u32 = (uint32_t)__cvta_generic_to_shared(smem_f);

    const int tid = threadIdx.x;
    const int c   = blockIdx.x;          // cluster rank / column slice
    const int b0  = blockIdx.y * ROWS;
    const int j0  = c * COLS;

    const int ks = tid >> 5;             // warp = k-slice (0..15)
    const int jp = tid & 31;             // cols 2jp, 2jp+1
    const int jj = tid >> 2;             // reduce mapping (tid<256)
    const int bb = tid & 3;

    // ---- R slice into registers ----
    float rx[KROWS], ry[KROWS];
    {
        const float* rg = R + j0 + 2 * jp;
#pragma unroll
        for (int ii = 0; ii < KROWS; ii++) {
            float2 v = *(const float2*)(rg + (ks * KROWS + ii) * D_);
            rx[ii] = v.x; ry[ii] = v.y;
        }
    }

    // ---- init smem ----
    for (int idx = tid; idx < 3 * D_ * ROWS; idx += THREADS) hbuf[idx] = 0.0f;
    if (tid < COLS) {
        bias[tid] = b_ig[j0 + tid];
        wsl[tid]  = W_out[j0 + tid];
    }
    if (tid < 32) osum[tid] = 0.0f;
    if (tid == 0) {
        mbar_init(smem_u32 + MBAR_BYTE + 0,  1);
        mbar_init(smem_u32 + MBAR_BYTE + 8,  1);
        mbar_init(smem_u32 + MBAR_BYTE + 16, 1);
    }
    __syncthreads();
    if (tid == 0) {
        mbar_expect_tx(smem_u32 + MBAR_BYTE + 0,  STEP_TX);
        mbar_expect_tx(smem_u32 + MBAR_BYTE + 8,  STEP_TX);
        mbar_expect_tx(smem_u32 + MBAR_BYTE + 16, STEP_TX);
    }
    __syncthreads();
    asm volatile("barrier.cluster.arrive.aligned;" ::: "memory");
    asm volatile("barrier.cluster.wait.aligned;"   ::: "memory");

    // Peer smem bases
    uint32_t peer_base[CSZ];
#pragma unroll
    for (int p = 0; p < CSZ; p++) {
        asm volatile("mapa.shared::cluster.u32 %0, %1, %2;"
                     : "=r"(peer_base[p]) : "r"(smem_u32), "r"(p));
    }

    float racc = 0.0f;
    int cur = 0;
    uint32_t phases = 0;   // bit b = next wait parity for buffer b

    for (int t = 0; t < L_; t++) {
        const int nxt = (cur == 2) ? 0 : cur + 1;

        // prefetch ci (consumed after matvec)
        float civ = 0.0f;
        if (tid < 256)
            civ = __ldg(&g_ci[((b0 + bb) * L_ + t) * D_ + j0 + jj]);

        // deferred output partial from step t-1 (pre-wait, off critical path)
        if (t > 0 && tid < 4) {
            float s = 0.0f;
#pragma unroll
            for (int w = 0; w < 8; w++) s += osum[w * 4 + tid];
            racc += s;
            g_part[(b0 + tid) * (CSZ * L_) + c * L_ + (t - 1)] = racc;
        }

        // wait for h(t) remote slices (skip t=0: zeros written locally)
        if (t > 0) {
            mbar_wait_cta(smem_u32 + MBAR_BYTE + cur * 8, (phases >> cur) & 1u);
            phases ^= (1u << cur);
            // re-post expect for this buffer's NEXT fill round (at step t+2)
            if (tid == 256)
                mbar_expect_tx(smem_u32 + MBAR_BYTE + cur * 8, STEP_TX);
        }

        const float* hc = hbuf + cur * (D_ * ROWS);

        // ---- matvec: R from registers, h broadcast from smem ----
        {
            const ulonglong2* hvp = (const ulonglong2*)(hc + ks * KROWS * ROWS);
            unsigned long long a00 = 0, a01 = 0, a10 = 0, a11 = 0;
#pragma unroll
            for (int ii = 0; ii < KROWS; ii++) {
                ulonglong2 hv = hvp[ii];
                unsigned long long r0 = pk2(rx[ii], rx[ii]);
                unsigned long long r1 = pk2(ry[ii], ry[ii]);
                fma2(a00, r0, hv.x); fma2(a01, r0, hv.y);
                fma2(a10, r1, hv.x); fma2(a11, r1, hv.y);
            }
            float4 q0, q1;
            upk2(q0.x, q0.y, a00); upk2(q0.z, q0.w, a01);
            upk2(q1.x, q1.y, a10); upk2(q1.z, q1.w, a11);
            float* pb = pbuf + (ks * 32 + jp) * 8;
            *(float4*)(pb)     = q0;
            *(float4*)(pb + 4) = q1;
        }
        __syncthreads();

        // ---- reduce + gate + update: write h(t+1) own slice locally ----
        if (tid < 256) {
            float z = bias[jj];
#pragma unroll
            for (int s = 0; s < 16; s++) z += pbuf[s * 256 + tid];
            float ig = 1.0f / (1.0f + __expf(-z));
            float u  = civ * ig;
            float hval = hc[(j0 + jj) * 4 + bb] + u;
            hbuf[nxt * (D_ * ROWS) + (j0 + jj) * 4 + bb] = hval;

            float pp = u * wsl[jj];
            pp += __shfl_xor_sync(0xFFFFFFFF, pp, 4);
            pp += __shfl_xor_sync(0xFFFFFFFF, pp, 8);
            pp += __shfl_xor_sync(0xFFFFFFFF, pp, 16);
            if ((tid & 31) < 4)
                osum[(tid >> 5) * 4 + bb] = pp;
        }
        __syncthreads();

        // ---- DMA h(t+1) own slice to the 7 REMOTE peers (skip self) ----
        if (t + 1 < L_ && tid < CSZ && tid != c) {
            fence_proxy_async_cta();
            uint32_t off  = (uint32_t)(HBUF_OFF + nxt * (D_ * ROWS) + j0 * 4) * 4u;
            uint32_t moff = (uint32_t)(MBAR_BYTE + nxt * 8);
            bulk_dsmem(peer_base[tid] + off, smem_u32 + off, SLICE_BYTES,
                       peer_base[tid] + moff);
        }

        cur = nxt;
    }

    // final deferred output partial (t = L-1)
    if (tid < 4) {
        float s = 0.0f;
#pragma unroll
        for (int w = 0; w < 8; w++) s += osum[w * 4 + tid];
        racc += s;
        g_part[(b0 + tid) * (CSZ * L_) + c * L_ + (L_ - 1)] = racc;
    }

    asm volatile("barrier.cluster.arrive.aligned;" ::: "memory");
    asm volatile("barrier.cluster.wait.aligned;"   ::: "memory");
}

// ============================================================================
// Kernel 3: out[b,t] = b_out + sum_c g_part[b][c][t]
// ============================================================================
__global__ __launch_bounds__(256)
void k_out(const float* __restrict__ b_out, float* __restrict__ out)
{
    int i = blockIdx.x * 256 + threadIdx.x;
    int b = i >> 9, t = i & 511;
    float s = b_out[0];
#pragma unroll
    for (int cc = 0; cc < CSZ; cc++) s += g_part[b * (CSZ * L_) + cc * L_ + t];
    out[i] = s;
}

// ============================================================================
extern "C" void kernel_launch(void* const* d_in, const int* in_sizes, int n_in,
                              void* d_out, int out_size)
{
    const float* obs  = (const float*)d_in[0];
    const float* act  = (const float*)d_in[1];
    const float* W_ci = (const float*)d_in[2];
    const float* b_ci = (const float*)d_in[3];
    const float* R    = (const float*)d_in[4];
    const float* bg   = (const float*)d_in[5];
    const float* W_o  = (const float*)d_in[6];
    const float* b_o  = (const float*)d_in[7];
    float* out = (float*)d_out;

    k_ci<<<dim3(8, 512), 256>>>(obs, act, W_ci, b_ci);

    cudaFuncSetAttribute(k_scan, cudaFuncAttributeMaxDynamicSharedMemorySize, SMEM_BYTES);
    k_scan<<<dim3(CSZ, NCL), THREADS, SMEM_BYTES>>>(R, bg, W_o);

    k_out<<<128, 256>>>(b_o, out);
}